// round 5
// baseline (speedup 1.0000x reference)
#include <cuda_runtime.h>

#define N_NODES  50000
#define N_EDGES  1600000
#define N_GRAPHS 1000

// ---------------- scratch (device globals; no allocation allowed) ----------
__device__ __align__(16) float g_aggr1[N_NODES * 8];    // layer1 aggregation (7 used, pad 8)
__device__ __align__(16) float g_h1[N_NODES * 64];      // layer1 output
__device__ __align__(16) float g_aggr2[N_NODES * 64];   // layer2 aggregation
__device__ __align__(16) float g_sums[N_GRAPHS * 64];   // pooled sums
__device__ __align__(16) float g_cnt[N_GRAPHS];         // per-graph node counts

// ---------------- zero scratch (vectorized) ---------------------------------
#define ZERO_TOTAL4 ((N_NODES * 8 + N_NODES * 64 + N_GRAPHS * 64) / 4)
__global__ void zero_kernel() {
    int i = blockIdx.x * blockDim.x + threadIdx.x;
    const float4 z4 = make_float4(0.f, 0.f, 0.f, 0.f);
    if (i < N_NODES * 2) {
        reinterpret_cast<float4*>(g_aggr1)[i] = z4;
    } else if (i < N_NODES * 2 + N_NODES * 16) {
        reinterpret_cast<float4*>(g_aggr2)[i - N_NODES * 2] = z4;
    } else if (i < ZERO_TOTAL4) {
        reinterpret_cast<float4*>(g_sums)[i - (N_NODES * 2 + N_NODES * 16)] = z4;
    }
    if (i < N_GRAPHS) g_cnt[i] = 0.f;
}

// ---------------- layer 1 edge pass (d = 7), grid-stride, register weights --
// msg = relu(x[src] + edge_attr @ We1 + be1); 2x red.v4 scatter to aggr1[dst]
__global__ void edge1_kernel(const float* __restrict__ x,
                             const float* __restrict__ ea,
                             const int*   __restrict__ ei,
                             const float* __restrict__ We1,
                             const float* __restrict__ be1) {
    float w[4][7], b[7];
#pragma unroll
    for (int i = 0; i < 4; i++)
#pragma unroll
        for (int j = 0; j < 7; j++)
            w[i][j] = __ldg(&We1[i * 7 + j]);
#pragma unroll
    for (int j = 0; j < 7; j++) b[j] = __ldg(&be1[j]);

    int t  = blockIdx.x * blockDim.x + threadIdx.x;
    int nt = gridDim.x * blockDim.x;
    for (int e = t; e < N_EDGES; e += nt) {
        int src = __ldg(&ei[e]);
        int dst = __ldg(&ei[N_EDGES + e]);
        float4 a = __ldg(reinterpret_cast<const float4*>(ea) + e);
        float v[8];
#pragma unroll
        for (int j = 0; j < 7; j++) {
            float m = b[j] + a.x * w[0][j] + a.y * w[1][j]
                            + a.z * w[2][j] + a.w * w[3][j];
            m += __ldg(&x[src * 7 + j]);
            v[j] = fmaxf(m, 0.f);
        }
        v[7] = 0.f;
        float* p = g_aggr1 + dst * 8;
        asm volatile("red.global.add.v4.f32 [%0], {%1, %2, %3, %4};"
                     :: "l"(p), "f"(v[0]), "f"(v[1]), "f"(v[2]), "f"(v[3]) : "memory");
        asm volatile("red.global.add.v4.f32 [%0], {%1, %2, %3, %4};"
                     :: "l"(p + 4), "f"(v[4]), "f"(v[5]), "f"(v[6]), "f"(v[7]) : "memory");
    }
}

// ---------------- layer 1 node MLP: 7 -> 64 -> 64, warp per node, persistent
__global__ void node1_kernel(const float* __restrict__ x,
                             const float* __restrict__ W1a,
                             const float* __restrict__ b1a,
                             const float* __restrict__ W1b,
                             const float* __restrict__ b1b) {
    __shared__ float sWa[7 * 64];
    __shared__ float sWb[64 * 64];
    __shared__ float sba[64];
    __shared__ float sbb[64];
    for (int i = threadIdx.x; i < 7 * 64; i += blockDim.x) sWa[i] = W1a[i];
    for (int i = threadIdx.x; i < 64 * 64; i += blockDim.x) sWb[i] = W1b[i];
    if (threadIdx.x < 64) { sba[threadIdx.x] = b1a[threadIdx.x]; sbb[threadIdx.x] = b1b[threadIdx.x]; }
    __syncthreads();

    int warp = (blockIdx.x * blockDim.x + threadIdx.x) >> 5;
    int nw   = (gridDim.x * blockDim.x) >> 5;
    int lane = threadIdx.x & 31;
    int j    = lane * 2;

    for (int node = warp; node < N_NODES; node += nw) {
        float z[7];
#pragma unroll
        for (int k = 0; k < 7; k++)
            z[k] = __ldg(&x[node * 7 + k]) + g_aggr1[node * 8 + k];

        float t0 = sba[j], t1 = sba[j + 1];
#pragma unroll
        for (int k = 0; k < 7; k++) {
            t0 += z[k] * sWa[k * 64 + j];
            t1 += z[k] * sWa[k * 64 + j + 1];
        }
        t0 = fmaxf(t0, 0.f);
        t1 = fmaxf(t1, 0.f);

        float a0 = sbb[j], a1 = sbb[j + 1];
#pragma unroll
        for (int k = 0; k < 64; k++) {
            float tk = __shfl_sync(0xffffffffu, (k & 1) ? t1 : t0, k >> 1);
            a0 += tk * sWb[k * 64 + j];
            a1 += tk * sWb[k * 64 + j + 1];
        }
        // outer relu from reference
        float2 o = make_float2(fmaxf(a0, 0.f), fmaxf(a1, 0.f));
        *reinterpret_cast<float2*>(g_h1 + node * 64 + j) = o;
    }
}

// ---------------- layer 2 edge pass (d = 64) --------------------------------
// half-warp owns 8 consecutive edges; weights in registers loaded ONCE;
// software-pipelined: prefetch edge i+1 while computing edge i (low regs).
#define E2_EPW 8   // edges per half-warp (N_EDGES divisible by this)
__global__ void __launch_bounds__(256)
edge2_kernel(const float* __restrict__ ea,
             const int*   __restrict__ ei,
             const float* __restrict__ We2,
             const float* __restrict__ be2) {
    int l    = threadIdx.x & 15;                       // output slice 4l..4l+3
    int hw   = (blockIdx.x * blockDim.x + threadIdx.x) >> 4;
    int base = hw * E2_EPW;

    // per-lane weights: columns 4l..4l+3 of We2 (4 input rows) + bias
    float4 t0 = __ldg(reinterpret_cast<const float4*>(We2 + 0 * 64) + l);
    float4 t1 = __ldg(reinterpret_cast<const float4*>(We2 + 1 * 64) + l);
    float4 t2 = __ldg(reinterpret_cast<const float4*>(We2 + 2 * 64) + l);
    float4 t3 = __ldg(reinterpret_cast<const float4*>(We2 + 3 * 64) + l);
    float4 bb = __ldg(reinterpret_cast<const float4*>(be2) + l);

    // prologue: prefetch edge 0
    int src = __ldg(&ei[base]);
    int dst = __ldg(&ei[N_EDGES + base]);
    float4 a = __ldg(reinterpret_cast<const float4*>(ea) + base);
    float4 h = __ldg(reinterpret_cast<const float4*>(g_h1 + src * 64) + l);

#pragma unroll
    for (int i = 0; i < E2_EPW; i++) {
        float4 ac = a;
        float4 hc = h;
        int    dc = dst;
        if (i + 1 < E2_EPW) {
            int e = base + i + 1;
            src = __ldg(&ei[e]);
            dst = __ldg(&ei[N_EDGES + e]);
            a   = __ldg(reinterpret_cast<const float4*>(ea) + e);
            h   = __ldg(reinterpret_cast<const float4*>(g_h1 + src * 64) + l);
        }
        float m0 = fmaxf(bb.x + ac.x*t0.x + ac.y*t1.x + ac.z*t2.x + ac.w*t3.x + hc.x, 0.f);
        float m1 = fmaxf(bb.y + ac.x*t0.y + ac.y*t1.y + ac.z*t2.y + ac.w*t3.y + hc.y, 0.f);
        float m2 = fmaxf(bb.z + ac.x*t0.z + ac.y*t1.z + ac.z*t2.z + ac.w*t3.z + hc.z, 0.f);
        float m3 = fmaxf(bb.w + ac.x*t0.w + ac.y*t1.w + ac.z*t2.w + ac.w*t3.w + hc.w, 0.f);
        float* p = g_aggr2 + dc * 64 + l * 4;
        asm volatile("red.global.add.v4.f32 [%0], {%1, %2, %3, %4};"
                     :: "l"(p), "f"(m0), "f"(m1), "f"(m2), "f"(m3) : "memory");
    }
}

// ---------------- layer 2 node MLP (64->64->64) + pool, persistent ---------
__global__ void node2pool_kernel(const int*   __restrict__ batch,
                                 const float* __restrict__ W2a,
                                 const float* __restrict__ b2a,
                                 const float* __restrict__ W2b,
                                 const float* __restrict__ b2b) {
    __shared__ float sWa[64 * 64];
    __shared__ float sWb[64 * 64];
    __shared__ float sba[64];
    __shared__ float sbb[64];
    for (int i = threadIdx.x; i < 64 * 64; i += blockDim.x) { sWa[i] = W2a[i]; sWb[i] = W2b[i]; }
    if (threadIdx.x < 64) { sba[threadIdx.x] = b2a[threadIdx.x]; sbb[threadIdx.x] = b2b[threadIdx.x]; }
    __syncthreads();

    int warp = (blockIdx.x * blockDim.x + threadIdx.x) >> 5;
    int nw   = (gridDim.x * blockDim.x) >> 5;
    int lane = threadIdx.x & 31;
    int j    = lane * 2;

    for (int node = warp; node < N_NODES; node += nw) {
        float2 hv = *reinterpret_cast<const float2*>(g_h1 + node * 64 + j);
        float2 av = *reinterpret_cast<const float2*>(g_aggr2 + node * 64 + j);
        float z0 = hv.x + av.x;
        float z1 = hv.y + av.y;

        float t0 = sba[j], t1 = sba[j + 1];
#pragma unroll
        for (int k = 0; k < 64; k++) {
            float zk = __shfl_sync(0xffffffffu, (k & 1) ? z1 : z0, k >> 1);
            t0 += zk * sWa[k * 64 + j];
            t1 += zk * sWa[k * 64 + j + 1];
        }
        t0 = fmaxf(t0, 0.f);
        t1 = fmaxf(t1, 0.f);

        float a0 = sbb[j], a1 = sbb[j + 1];
#pragma unroll
        for (int k = 0; k < 64; k++) {
            float tk = __shfl_sync(0xffffffffu, (k & 1) ? t1 : t0, k >> 1);
            a0 += tk * sWb[k * 64 + j];
            a1 += tk * sWb[k * 64 + j + 1];
        }
        a0 = fmaxf(a0, 0.f);   // outer relu from reference
        a1 = fmaxf(a1, 0.f);

        int g = batch[node];
        float* p = g_sums + g * 64 + j;
        asm volatile("red.global.add.v2.f32 [%0], {%1, %2};"
                     :: "l"(p), "f"(a0), "f"(a1) : "memory");
        if (lane == 0) atomicAdd(&g_cnt[g], 1.0f);
    }
}

// ---------------- final FC: pooled[G,64] @ Wfc[64,12] + bfc -----------------
__global__ void fc_kernel(const float* __restrict__ Wfc,
                          const float* __restrict__ bfc,
                          float* __restrict__ out) {
    int i = blockIdx.x * blockDim.x + threadIdx.x;
    if (i >= N_GRAPHS * 12) return;
    int g = i / 12;
    int c = i % 12;
    float inv = 1.0f / fmaxf(g_cnt[g], 1.0f);
    float acc = 0.f;
#pragma unroll
    for (int k = 0; k < 64; k++)
        acc += g_sums[g * 64 + k] * Wfc[k * 12 + c];
    out[i] = bfc[c] + inv * acc;
}

// ---------------- launch ----------------------------------------------------
extern "C" void kernel_launch(void* const* d_in, const int* in_sizes, int n_in,
                              void* d_out, int out_size) {
    const float* x    = (const float*)d_in[0];
    const float* ea   = (const float*)d_in[1];
    const int*   ei   = (const int*)  d_in[2];
    const int*   batch= (const int*)  d_in[3];
    const float* We1  = (const float*)d_in[4];
    const float* be1  = (const float*)d_in[5];
    const float* W1a  = (const float*)d_in[6];
    const float* b1a  = (const float*)d_in[7];
    const float* W1b  = (const float*)d_in[8];
    const float* b1b  = (const float*)d_in[9];
    const float* We2  = (const float*)d_in[10];
    const float* be2  = (const float*)d_in[11];
    const float* W2a  = (const float*)d_in[12];
    const float* b2a  = (const float*)d_in[13];
    const float* W2b  = (const float*)d_in[14];
    const float* b2b  = (const float*)d_in[15];
    const float* Wfc  = (const float*)d_in[16];
    const float* bfc  = (const float*)d_in[17];
    float* out = (float*)d_out;

    zero_kernel<<<(ZERO_TOTAL4 + 255) / 256, 256>>>();
    edge1_kernel<<<1184, 256>>>(x, ea, ei, We1, be1);
    node1_kernel<<<592, 256>>>(x, W1a, b1a, W1b, b1b);
    edge2_kernel<<<(N_EDGES / E2_EPW) * 16 / 256, 256>>>(ea, ei, We2, be2);
    node2pool_kernel<<<592, 256>>>(batch, W2a, b2a, W2b, b2b);
    fc_kernel<<<(N_GRAPHS * 12 + 255) / 256, 256>>>(Wfc, bfc, out);
}

// round 6
// speedup vs baseline: 1.3446x; 1.3446x over previous
#include <cuda_runtime.h>

#define N_NODES  50000
#define N_EDGES  1600000
#define N_GRAPHS 1000

// ---------------- scratch (device globals; no allocation allowed) ----------
__device__ __align__(16) float g_x8[N_NODES * 8];       // padded node features
__device__ __align__(16) float g_aggr1[N_NODES * 8];    // layer1 aggregation (7 used, pad 8)
__device__ __align__(16) float g_h1[N_NODES * 64];      // layer1 output
__device__ __align__(16) float g_aggr2[N_NODES * 64];   // layer2 aggregation
__device__ __align__(16) float g_sums[N_GRAPHS * 64];   // pooled sums
__device__ __align__(16) float g_cnt[N_GRAPHS];         // per-graph node counts

// ---------------- zero scratch + pad x ---------------------------------------
#define ZERO_TOTAL4 ((N_NODES * 8 + N_NODES * 64 + N_GRAPHS * 64) / 4)
__global__ void zero_kernel(const float* __restrict__ x) {
    int i = blockIdx.x * blockDim.x + threadIdx.x;
    const float4 z4 = make_float4(0.f, 0.f, 0.f, 0.f);
    if (i < N_NODES * 2) {
        reinterpret_cast<float4*>(g_aggr1)[i] = z4;
        // pad x: thread i covers node i>>1, half i&1
        int node = i >> 1, h = i & 1;
        int base = node * 7 + h * 4;
        float4 v;
        v.x = __ldg(&x[base + 0]);
        v.y = __ldg(&x[base + 1]);
        v.z = __ldg(&x[base + 2]);
        v.w = (h == 0) ? __ldg(&x[base + 3]) : 0.f;   // j=7 pad
        reinterpret_cast<float4*>(g_x8)[i] = v;
    } else if (i < N_NODES * 2 + N_NODES * 16) {
        reinterpret_cast<float4*>(g_aggr2)[i - N_NODES * 2] = z4;
    } else if (i < ZERO_TOTAL4) {
        reinterpret_cast<float4*>(g_sums)[i - (N_NODES * 2 + N_NODES * 16)] = z4;
    }
    if (i < N_GRAPHS) g_cnt[i] = 0.f;
}

// ---------------- layer 1 edge pass (d = 7), grid-stride, register weights --
// msg = relu(x8[src] + edge_attr @ We1 + be1); 2x red.v4 scatter to aggr1[dst]
__global__ void edge1_kernel(const float* __restrict__ ea,
                             const int*   __restrict__ ei,
                             const float* __restrict__ We1,
                             const float* __restrict__ be1) {
    float w[4][7], b[7];
#pragma unroll
    for (int i = 0; i < 4; i++)
#pragma unroll
        for (int j = 0; j < 7; j++)
            w[i][j] = __ldg(&We1[i * 7 + j]);
#pragma unroll
    for (int j = 0; j < 7; j++) b[j] = __ldg(&be1[j]);

    int t  = blockIdx.x * blockDim.x + threadIdx.x;
    int nt = gridDim.x * blockDim.x;
    for (int e = t; e < N_EDGES; e += nt) {
        int src = __ldg(&ei[e]);
        int dst = __ldg(&ei[N_EDGES + e]);
        float4 a  = __ldg(reinterpret_cast<const float4*>(ea) + e);
        float4 x0 = __ldg(reinterpret_cast<const float4*>(g_x8) + src * 2);
        float4 x1 = __ldg(reinterpret_cast<const float4*>(g_x8) + src * 2 + 1);
        float xs[8] = {x0.x, x0.y, x0.z, x0.w, x1.x, x1.y, x1.z, 0.f};
        float v[8];
#pragma unroll
        for (int j = 0; j < 7; j++) {
            float m = b[j] + a.x * w[0][j] + a.y * w[1][j]
                            + a.z * w[2][j] + a.w * w[3][j];
            v[j] = fmaxf(m + xs[j], 0.f);
        }
        v[7] = 0.f;
        float* p = g_aggr1 + dst * 8;
        asm volatile("red.global.add.v4.f32 [%0], {%1, %2, %3, %4};"
                     :: "l"(p), "f"(v[0]), "f"(v[1]), "f"(v[2]), "f"(v[3]) : "memory");
        asm volatile("red.global.add.v4.f32 [%0], {%1, %2, %3, %4};"
                     :: "l"(p + 4), "f"(v[4]), "f"(v[5]), "f"(v[6]), "f"(v[7]) : "memory");
    }
}

// ---------------- layer 1 node MLP: 7 -> 64 -> 64, 4-node blocked ----------
#define N_GROUPS (N_NODES / 4)
__global__ void node1_kernel(const float* __restrict__ W1a,
                             const float* __restrict__ b1a,
                             const float* __restrict__ W1b,
                             const float* __restrict__ b1b) {
    __shared__ float2 sWa[7 * 32];
    __shared__ float2 sWb[64 * 32];
    __shared__ float  sba[64];
    __shared__ float  sbb[64];
    for (int i = threadIdx.x; i < 7 * 32; i += blockDim.x)
        sWa[i] = reinterpret_cast<const float2*>(W1a)[i];
    for (int i = threadIdx.x; i < 64 * 32; i += blockDim.x)
        sWb[i] = reinterpret_cast<const float2*>(W1b)[i];
    if (threadIdx.x < 64) { sba[threadIdx.x] = b1a[threadIdx.x]; sbb[threadIdx.x] = b1b[threadIdx.x]; }
    __syncthreads();

    int warp = (blockIdx.x * blockDim.x + threadIdx.x) >> 5;
    int nw   = (gridDim.x * blockDim.x) >> 5;
    int lane = threadIdx.x & 31;
    int j    = lane * 2;

    for (int grp = warp; grp < N_GROUPS; grp += nw) {
        int n0 = grp * 4;
        float z[4][7];
#pragma unroll
        for (int m = 0; m < 4; m++)
#pragma unroll
            for (int k = 0; k < 7; k++)
                z[m][k] = g_x8[(n0 + m) * 8 + k] + g_aggr1[(n0 + m) * 8 + k];

        float t0[4], t1[4];
#pragma unroll
        for (int m = 0; m < 4; m++) { t0[m] = sba[j]; t1[m] = sba[j + 1]; }
#pragma unroll
        for (int k = 0; k < 7; k++) {
            float2 w = sWa[k * 32 + lane];
#pragma unroll
            for (int m = 0; m < 4; m++) {
                t0[m] += z[m][k] * w.x;
                t1[m] += z[m][k] * w.y;
            }
        }
#pragma unroll
        for (int m = 0; m < 4; m++) { t0[m] = fmaxf(t0[m], 0.f); t1[m] = fmaxf(t1[m], 0.f); }

        float a0[4], a1[4];
#pragma unroll
        for (int m = 0; m < 4; m++) { a0[m] = sbb[j]; a1[m] = sbb[j + 1]; }
#pragma unroll
        for (int k = 0; k < 64; k++) {
            float2 w = sWb[k * 32 + lane];
#pragma unroll
            for (int m = 0; m < 4; m++) {
                float tk = __shfl_sync(0xffffffffu, (k & 1) ? t1[m] : t0[m], k >> 1);
                a0[m] += tk * w.x;
                a1[m] += tk * w.y;
            }
        }
#pragma unroll
        for (int m = 0; m < 4; m++) {
            float2 o = make_float2(fmaxf(a0[m], 0.f), fmaxf(a1[m], 0.f));
            *reinterpret_cast<float2*>(g_h1 + (n0 + m) * 64 + j) = o;
        }
    }
}

// ---------------- layer 2 edge pass (d = 64) --------------------------------
// half-warp owns 8 consecutive edges; weights in registers loaded ONCE;
// pair-unrolled for MLP; launch_bounds caps regs at 64 -> 50% occupancy.
#define E2_EPW 8
__global__ void __launch_bounds__(256, 4)
edge2_kernel(const float* __restrict__ ea,
             const int*   __restrict__ ei,
             const float* __restrict__ We2,
             const float* __restrict__ be2) {
    int l    = threadIdx.x & 15;                       // output slice 4l..4l+3
    int hw   = (blockIdx.x * blockDim.x + threadIdx.x) >> 4;
    int base = hw * E2_EPW;

    float4 t0 = __ldg(reinterpret_cast<const float4*>(We2 + 0 * 64) + l);
    float4 t1 = __ldg(reinterpret_cast<const float4*>(We2 + 1 * 64) + l);
    float4 t2 = __ldg(reinterpret_cast<const float4*>(We2 + 2 * 64) + l);
    float4 t3 = __ldg(reinterpret_cast<const float4*>(We2 + 3 * 64) + l);
    float4 bb = __ldg(reinterpret_cast<const float4*>(be2) + l);

#pragma unroll
    for (int i = 0; i < E2_EPW; i += 2) {
        int e0 = base + i;
        int e1 = base + i + 1;
        int src0 = __ldg(&ei[e0]);
        int src1 = __ldg(&ei[e1]);
        int dst0 = __ldg(&ei[N_EDGES + e0]);
        int dst1 = __ldg(&ei[N_EDGES + e1]);
        float4 a0 = __ldg(reinterpret_cast<const float4*>(ea) + e0);
        float4 a1 = __ldg(reinterpret_cast<const float4*>(ea) + e1);
        float4 h0 = __ldg(reinterpret_cast<const float4*>(g_h1 + src0 * 64) + l);
        float4 h1 = __ldg(reinterpret_cast<const float4*>(g_h1 + src1 * 64) + l);

        float m0 = fmaxf(bb.x + a0.x*t0.x + a0.y*t1.x + a0.z*t2.x + a0.w*t3.x + h0.x, 0.f);
        float m1 = fmaxf(bb.y + a0.x*t0.y + a0.y*t1.y + a0.z*t2.y + a0.w*t3.y + h0.y, 0.f);
        float m2 = fmaxf(bb.z + a0.x*t0.z + a0.y*t1.z + a0.z*t2.z + a0.w*t3.z + h0.z, 0.f);
        float m3 = fmaxf(bb.w + a0.x*t0.w + a0.y*t1.w + a0.z*t2.w + a0.w*t3.w + h0.w, 0.f);
        float* p0 = g_aggr2 + dst0 * 64 + l * 4;
        asm volatile("red.global.add.v4.f32 [%0], {%1, %2, %3, %4};"
                     :: "l"(p0), "f"(m0), "f"(m1), "f"(m2), "f"(m3) : "memory");

        float n0 = fmaxf(bb.x + a1.x*t0.x + a1.y*t1.x + a1.z*t2.x + a1.w*t3.x + h1.x, 0.f);
        float n1 = fmaxf(bb.y + a1.x*t0.y + a1.y*t1.y + a1.z*t2.y + a1.w*t3.y + h1.y, 0.f);
        float n2 = fmaxf(bb.z + a1.x*t0.z + a1.y*t1.z + a1.z*t2.z + a1.w*t3.z + h1.z, 0.f);
        float n3 = fmaxf(bb.w + a1.x*t0.w + a1.y*t1.w + a1.z*t2.w + a1.w*t3.w + h1.w, 0.f);
        float* p1 = g_aggr2 + dst1 * 64 + l * 4;
        asm volatile("red.global.add.v4.f32 [%0], {%1, %2, %3, %4};"
                     :: "l"(p1), "f"(n0), "f"(n1), "f"(n2), "f"(n3) : "memory");
    }
}

// ---------------- layer 2 node MLP (64->64->64) + pool, 4-node blocked -----
__global__ void node2pool_kernel(const int*   __restrict__ batch,
                                 const float* __restrict__ W2a,
                                 const float* __restrict__ b2a,
                                 const float* __restrict__ W2b,
                                 const float* __restrict__ b2b) {
    __shared__ float2 sWa[64 * 32];
    __shared__ float2 sWb[64 * 32];
    __shared__ float  sba[64];
    __shared__ float  sbb[64];
    for (int i = threadIdx.x; i < 64 * 32; i += blockDim.x) {
        sWa[i] = reinterpret_cast<const float2*>(W2a)[i];
        sWb[i] = reinterpret_cast<const float2*>(W2b)[i];
    }
    if (threadIdx.x < 64) { sba[threadIdx.x] = b2a[threadIdx.x]; sbb[threadIdx.x] = b2b[threadIdx.x]; }
    __syncthreads();

    int warp = (blockIdx.x * blockDim.x + threadIdx.x) >> 5;
    int nw   = (gridDim.x * blockDim.x) >> 5;
    int lane = threadIdx.x & 31;
    int j    = lane * 2;

    for (int grp = warp; grp < N_GROUPS; grp += nw) {
        int n0 = grp * 4;
        float z0[4], z1[4];
#pragma unroll
        for (int m = 0; m < 4; m++) {
            float2 hv = *reinterpret_cast<const float2*>(g_h1 + (n0 + m) * 64 + j);
            float2 av = *reinterpret_cast<const float2*>(g_aggr2 + (n0 + m) * 64 + j);
            z0[m] = hv.x + av.x;
            z1[m] = hv.y + av.y;
        }

        float t0[4], t1[4];
#pragma unroll
        for (int m = 0; m < 4; m++) { t0[m] = sba[j]; t1[m] = sba[j + 1]; }
#pragma unroll
        for (int k = 0; k < 64; k++) {
            float2 w = sWa[k * 32 + lane];
#pragma unroll
            for (int m = 0; m < 4; m++) {
                float zk = __shfl_sync(0xffffffffu, (k & 1) ? z1[m] : z0[m], k >> 1);
                t0[m] += zk * w.x;
                t1[m] += zk * w.y;
            }
        }
#pragma unroll
        for (int m = 0; m < 4; m++) { t0[m] = fmaxf(t0[m], 0.f); t1[m] = fmaxf(t1[m], 0.f); }

        float a0[4], a1[4];
#pragma unroll
        for (int m = 0; m < 4; m++) { a0[m] = sbb[j]; a1[m] = sbb[j + 1]; }
#pragma unroll
        for (int k = 0; k < 64; k++) {
            float2 w = sWb[k * 32 + lane];
#pragma unroll
            for (int m = 0; m < 4; m++) {
                float tk = __shfl_sync(0xffffffffu, (k & 1) ? t1[m] : t0[m], k >> 1);
                a0[m] += tk * w.x;
                a1[m] += tk * w.y;
            }
        }
#pragma unroll
        for (int m = 0; m < 4; m++) {
            float v0 = fmaxf(a0[m], 0.f);   // outer relu from reference
            float v1 = fmaxf(a1[m], 0.f);
            int g = batch[n0 + m];
            float* p = g_sums + g * 64 + j;
            asm volatile("red.global.add.v2.f32 [%0], {%1, %2};"
                         :: "l"(p), "f"(v0), "f"(v1) : "memory");
            if (lane == 0) atomicAdd(&g_cnt[g], 1.0f);
        }
    }
}

// ---------------- final FC: pooled[G,64] @ Wfc[64,12] + bfc -----------------
__global__ void fc_kernel(const float* __restrict__ Wfc,
                          const float* __restrict__ bfc,
                          float* __restrict__ out) {
    int i = blockIdx.x * blockDim.x + threadIdx.x;
    if (i >= N_GRAPHS * 12) return;
    int g = i / 12;
    int c = i % 12;
    float inv = 1.0f / fmaxf(g_cnt[g], 1.0f);
    float acc = 0.f;
#pragma unroll
    for (int k = 0; k < 64; k++)
        acc += g_sums[g * 64 + k] * Wfc[k * 12 + c];
    out[i] = bfc[c] + inv * acc;
}

// ---------------- launch ----------------------------------------------------
extern "C" void kernel_launch(void* const* d_in, const int* in_sizes, int n_in,
                              void* d_out, int out_size) {
    const float* x    = (const float*)d_in[0];
    const float* ea   = (const float*)d_in[1];
    const int*   ei   = (const int*)  d_in[2];
    const int*   batch= (const int*)  d_in[3];
    const float* We1  = (const float*)d_in[4];
    const float* be1  = (const float*)d_in[5];
    const float* W1a  = (const float*)d_in[6];
    const float* b1a  = (const float*)d_in[7];
    const float* W1b  = (const float*)d_in[8];
    const float* b1b  = (const float*)d_in[9];
    const float* We2  = (const float*)d_in[10];
    const float* be2  = (const float*)d_in[11];
    const float* W2a  = (const float*)d_in[12];
    const float* b2a  = (const float*)d_in[13];
    const float* W2b  = (const float*)d_in[14];
    const float* b2b  = (const float*)d_in[15];
    const float* Wfc  = (const float*)d_in[16];
    const float* bfc  = (const float*)d_in[17];
    float* out = (float*)d_out;

    zero_kernel<<<(ZERO_TOTAL4 + 255) / 256, 256>>>(x);
    edge1_kernel<<<1184, 256>>>(ea, ei, We1, be1);
    node1_kernel<<<592, 256>>>(W1a, b1a, W1b, b1b);
    edge2_kernel<<<(N_EDGES / E2_EPW) * 16 / 256, 256>>>(ea, ei, We2, be2);
    node2pool_kernel<<<592, 256>>>(batch, W2a, b2a, W2b, b2b);
    fc_kernel<<<(N_GRAPHS * 12 + 255) / 256, 256>>>(Wfc, bfc, out);
}

// round 7
// speedup vs baseline: 1.3765x; 1.0237x over previous
#include <cuda_runtime.h>
#include <cuda_fp16.h>

#define N_NODES  50000
#define N_EDGES  1600000
#define N_GRAPHS 1000

// ---------------- scratch (device globals; no allocation allowed) ----------
__device__ __align__(16) float  g_x8[N_NODES * 8];      // padded node features
__device__ __align__(16) float  g_aggr1[N_NODES * 8];   // layer1 aggregation (7 used, pad 8)
__device__ __align__(16) float  g_h1[N_NODES * 64];     // layer1 output (fp32)
__device__ __align__(16) __half g_h1h[N_NODES * 64];    // layer1 output (fp16 gather copy)
__device__ __align__(16) float  g_aggr2[N_NODES * 64];  // layer2 aggregation
__device__ __align__(16) float  g_sums[N_GRAPHS * 64];  // pooled sums
__device__ __align__(16) float  g_cnt[N_GRAPHS];        // per-graph node counts

// ---------------- zero scratch + pad x ---------------------------------------
#define ZERO_TOTAL4 ((N_NODES * 8 + N_NODES * 64 + N_GRAPHS * 64) / 4)
__global__ void zero_kernel(const float* __restrict__ x) {
    int i = blockIdx.x * blockDim.x + threadIdx.x;
    const float4 z4 = make_float4(0.f, 0.f, 0.f, 0.f);
    if (i < N_NODES * 2) {
        reinterpret_cast<float4*>(g_aggr1)[i] = z4;
        // pad x: thread i covers node i>>1, half i&1
        int node = i >> 1, h = i & 1;
        int base = node * 7 + h * 4;
        float4 v;
        v.x = __ldg(&x[base + 0]);
        v.y = __ldg(&x[base + 1]);
        v.z = __ldg(&x[base + 2]);
        v.w = (h == 0) ? __ldg(&x[base + 3]) : 0.f;   // j=7 pad
        reinterpret_cast<float4*>(g_x8)[i] = v;
    } else if (i < N_NODES * 2 + N_NODES * 16) {
        reinterpret_cast<float4*>(g_aggr2)[i - N_NODES * 2] = z4;
    } else if (i < ZERO_TOTAL4) {
        reinterpret_cast<float4*>(g_sums)[i - (N_NODES * 2 + N_NODES * 16)] = z4;
    }
    if (i < N_GRAPHS) g_cnt[i] = 0.f;
}

// ---------------- layer 1 edge pass (d = 7), grid-stride, register weights --
__global__ void edge1_kernel(const float* __restrict__ ea,
                             const int*   __restrict__ ei,
                             const float* __restrict__ We1,
                             const float* __restrict__ be1) {
    float w[4][7], b[7];
#pragma unroll
    for (int i = 0; i < 4; i++)
#pragma unroll
        for (int j = 0; j < 7; j++)
            w[i][j] = __ldg(&We1[i * 7 + j]);
#pragma unroll
    for (int j = 0; j < 7; j++) b[j] = __ldg(&be1[j]);

    int t  = blockIdx.x * blockDim.x + threadIdx.x;
    int nt = gridDim.x * blockDim.x;
    for (int e = t; e < N_EDGES; e += nt) {
        int src = __ldg(&ei[e]);
        int dst = __ldg(&ei[N_EDGES + e]);
        float4 a  = __ldg(reinterpret_cast<const float4*>(ea) + e);
        float4 x0 = __ldg(reinterpret_cast<const float4*>(g_x8) + src * 2);
        float4 x1 = __ldg(reinterpret_cast<const float4*>(g_x8) + src * 2 + 1);
        float xs[8] = {x0.x, x0.y, x0.z, x0.w, x1.x, x1.y, x1.z, 0.f};
        float v[8];
#pragma unroll
        for (int j = 0; j < 7; j++) {
            float m = b[j] + a.x * w[0][j] + a.y * w[1][j]
                            + a.z * w[2][j] + a.w * w[3][j];
            v[j] = fmaxf(m + xs[j], 0.f);
        }
        v[7] = 0.f;
        float* p = g_aggr1 + dst * 8;
        asm volatile("red.global.add.v4.f32 [%0], {%1, %2, %3, %4};"
                     :: "l"(p), "f"(v[0]), "f"(v[1]), "f"(v[2]), "f"(v[3]) : "memory");
        asm volatile("red.global.add.v4.f32 [%0], {%1, %2, %3, %4};"
                     :: "l"(p + 4), "f"(v[4]), "f"(v[5]), "f"(v[6]), "f"(v[7]) : "memory");
    }
}

// ---------------- layer 1 node MLP: 7 -> 64 -> 64, 4-node blocked ----------
#define N_GROUPS (N_NODES / 4)
__global__ void node1_kernel(const float* __restrict__ W1a,
                             const float* __restrict__ b1a,
                             const float* __restrict__ W1b,
                             const float* __restrict__ b1b) {
    __shared__ float2 sWa[7 * 32];
    __shared__ float2 sWb[64 * 32];
    __shared__ float  sba[64];
    __shared__ float  sbb[64];
    for (int i = threadIdx.x; i < 7 * 32; i += blockDim.x)
        sWa[i] = reinterpret_cast<const float2*>(W1a)[i];
    for (int i = threadIdx.x; i < 64 * 32; i += blockDim.x)
        sWb[i] = reinterpret_cast<const float2*>(W1b)[i];
    if (threadIdx.x < 64) { sba[threadIdx.x] = b1a[threadIdx.x]; sbb[threadIdx.x] = b1b[threadIdx.x]; }
    __syncthreads();

    int warp = (blockIdx.x * blockDim.x + threadIdx.x) >> 5;
    int nw   = (gridDim.x * blockDim.x) >> 5;
    int lane = threadIdx.x & 31;
    int j    = lane * 2;

    for (int grp = warp; grp < N_GROUPS; grp += nw) {
        int n0 = grp * 4;
        float z[4][7];
#pragma unroll
        for (int m = 0; m < 4; m++)
#pragma unroll
            for (int k = 0; k < 7; k++)
                z[m][k] = g_x8[(n0 + m) * 8 + k] + g_aggr1[(n0 + m) * 8 + k];

        float t0[4], t1[4];
#pragma unroll
        for (int m = 0; m < 4; m++) { t0[m] = sba[j]; t1[m] = sba[j + 1]; }
#pragma unroll
        for (int k = 0; k < 7; k++) {
            float2 w = sWa[k * 32 + lane];
#pragma unroll
            for (int m = 0; m < 4; m++) {
                t0[m] += z[m][k] * w.x;
                t1[m] += z[m][k] * w.y;
            }
        }
#pragma unroll
        for (int m = 0; m < 4; m++) { t0[m] = fmaxf(t0[m], 0.f); t1[m] = fmaxf(t1[m], 0.f); }

        float a0[4], a1[4];
#pragma unroll
        for (int m = 0; m < 4; m++) { a0[m] = sbb[j]; a1[m] = sbb[j + 1]; }
#pragma unroll
        for (int k = 0; k < 64; k++) {
            float2 w = sWb[k * 32 + lane];
#pragma unroll
            for (int m = 0; m < 4; m++) {
                float tk = __shfl_sync(0xffffffffu, (k & 1) ? t1[m] : t0[m], k >> 1);
                a0[m] += tk * w.x;
                a1[m] += tk * w.y;
            }
        }
#pragma unroll
        for (int m = 0; m < 4; m++) {
            float v0 = fmaxf(a0[m], 0.f);   // outer relu from reference
            float v1 = fmaxf(a1[m], 0.f);
            *reinterpret_cast<float2*>(g_h1 + (n0 + m) * 64 + j) = make_float2(v0, v1);
            // fp16 gather copy for edge2
            *reinterpret_cast<__half2*>(g_h1h + (n0 + m) * 64 + j) =
                __floats2half2_rn(v0, v1);
        }
    }
}

// ---------------- layer 2 edge pass (d = 64) --------------------------------
// half-warp owns 8 consecutive edges; weights in registers loaded ONCE;
// pair-unrolled; h1 gathered in fp16 (halves gather traffic & wavefronts).
#define E2_EPW 8
__global__ void __launch_bounds__(256, 4)
edge2_kernel(const float* __restrict__ ea,
             const int*   __restrict__ ei,
             const float* __restrict__ We2,
             const float* __restrict__ be2) {
    int l    = threadIdx.x & 15;                       // output slice 4l..4l+3
    int hw   = (blockIdx.x * blockDim.x + threadIdx.x) >> 4;
    int base = hw * E2_EPW;

    float4 t0 = __ldg(reinterpret_cast<const float4*>(We2 + 0 * 64) + l);
    float4 t1 = __ldg(reinterpret_cast<const float4*>(We2 + 1 * 64) + l);
    float4 t2 = __ldg(reinterpret_cast<const float4*>(We2 + 2 * 64) + l);
    float4 t3 = __ldg(reinterpret_cast<const float4*>(We2 + 3 * 64) + l);
    float4 bb = __ldg(reinterpret_cast<const float4*>(be2) + l);

#pragma unroll
    for (int i = 0; i < E2_EPW; i += 2) {
        int e0 = base + i;
        // vectorized index loads: consecutive (e0, e0+1) pairs
        int2 s01 = __ldg(reinterpret_cast<const int2*>(ei + e0));
        int2 d01 = __ldg(reinterpret_cast<const int2*>(ei + N_EDGES + e0));
        float4 a0 = __ldg(reinterpret_cast<const float4*>(ea) + e0);
        float4 a1 = __ldg(reinterpret_cast<const float4*>(ea) + e0 + 1);
        // fp16 gathers: 8 bytes per lane -> 128B per half-warp (1 line)
        uint2 hr0 = __ldg(reinterpret_cast<const uint2*>(g_h1h + s01.x * 64) + l);
        uint2 hr1 = __ldg(reinterpret_cast<const uint2*>(g_h1h + s01.y * 64) + l);
        float2 h00 = __half22float2(*reinterpret_cast<__half2*>(&hr0.x));
        float2 h01 = __half22float2(*reinterpret_cast<__half2*>(&hr0.y));
        float2 h10 = __half22float2(*reinterpret_cast<__half2*>(&hr1.x));
        float2 h11 = __half22float2(*reinterpret_cast<__half2*>(&hr1.y));

        float m0 = fmaxf(bb.x + a0.x*t0.x + a0.y*t1.x + a0.z*t2.x + a0.w*t3.x + h00.x, 0.f);
        float m1 = fmaxf(bb.y + a0.x*t0.y + a0.y*t1.y + a0.z*t2.y + a0.w*t3.y + h00.y, 0.f);
        float m2 = fmaxf(bb.z + a0.x*t0.z + a0.y*t1.z + a0.z*t2.z + a0.w*t3.z + h01.x, 0.f);
        float m3 = fmaxf(bb.w + a0.x*t0.w + a0.y*t1.w + a0.z*t2.w + a0.w*t3.w + h01.y, 0.f);
        float* p0 = g_aggr2 + d01.x * 64 + l * 4;
        asm volatile("red.global.add.v4.f32 [%0], {%1, %2, %3, %4};"
                     :: "l"(p0), "f"(m0), "f"(m1), "f"(m2), "f"(m3) : "memory");

        float n0 = fmaxf(bb.x + a1.x*t0.x + a1.y*t1.x + a1.z*t2.x + a1.w*t3.x + h10.x, 0.f);
        float n1 = fmaxf(bb.y + a1.x*t0.y + a1.y*t1.y + a1.z*t2.y + a1.w*t3.y + h10.y, 0.f);
        float n2 = fmaxf(bb.z + a1.x*t0.z + a1.y*t1.z + a1.z*t2.z + a1.w*t3.z + h11.x, 0.f);
        float n3 = fmaxf(bb.w + a1.x*t0.w + a1.y*t1.w + a1.z*t2.w + a1.w*t3.w + h11.y, 0.f);
        float* p1 = g_aggr2 + d01.y * 64 + l * 4;
        asm volatile("red.global.add.v4.f32 [%0], {%1, %2, %3, %4};"
                     :: "l"(p1), "f"(n0), "f"(n1), "f"(n2), "f"(n3) : "memory");
    }
}

// ---------------- layer 2 node MLP (64->64->64) + pool, 4-node blocked -----
__global__ void node2pool_kernel(const int*   __restrict__ batch,
                                 const float* __restrict__ W2a,
                                 const float* __restrict__ b2a,
                                 const float* __restrict__ W2b,
                                 const float* __restrict__ b2b) {
    __shared__ float2 sWa[64 * 32];
    __shared__ float2 sWb[64 * 32];
    __shared__ float  sba[64];
    __shared__ float  sbb[64];
    for (int i = threadIdx.x; i < 64 * 32; i += blockDim.x) {
        sWa[i] = reinterpret_cast<const float2*>(W2a)[i];
        sWb[i] = reinterpret_cast<const float2*>(W2b)[i];
    }
    if (threadIdx.x < 64) { sba[threadIdx.x] = b2a[threadIdx.x]; sbb[threadIdx.x] = b2b[threadIdx.x]; }
    __syncthreads();

    int warp = (blockIdx.x * blockDim.x + threadIdx.x) >> 5;
    int nw   = (gridDim.x * blockDim.x) >> 5;
    int lane = threadIdx.x & 31;
    int j    = lane * 2;

    for (int grp = warp; grp < N_GROUPS; grp += nw) {
        int n0 = grp * 4;
        float z0[4], z1[4];
#pragma unroll
        for (int m = 0; m < 4; m++) {
            float2 hv = *reinterpret_cast<const float2*>(g_h1 + (n0 + m) * 64 + j);
            float2 av = *reinterpret_cast<const float2*>(g_aggr2 + (n0 + m) * 64 + j);
            z0[m] = hv.x + av.x;
            z1[m] = hv.y + av.y;
        }

        float t0[4], t1[4];
#pragma unroll
        for (int m = 0; m < 4; m++) { t0[m] = sba[j]; t1[m] = sba[j + 1]; }
#pragma unroll
        for (int k = 0; k < 64; k++) {
            float2 w = sWa[k * 32 + lane];
#pragma unroll
            for (int m = 0; m < 4; m++) {
                float zk = __shfl_sync(0xffffffffu, (k & 1) ? z1[m] : z0[m], k >> 1);
                t0[m] += zk * w.x;
                t1[m] += zk * w.y;
            }
        }
#pragma unroll
        for (int m = 0; m < 4; m++) { t0[m] = fmaxf(t0[m], 0.f); t1[m] = fmaxf(t1[m], 0.f); }

        float a0[4], a1[4];
#pragma unroll
        for (int m = 0; m < 4; m++) { a0[m] = sbb[j]; a1[m] = sbb[j + 1]; }
#pragma unroll
        for (int k = 0; k < 64; k++) {
            float2 w = sWb[k * 32 + lane];
#pragma unroll
            for (int m = 0; m < 4; m++) {
                float tk = __shfl_sync(0xffffffffu, (k & 1) ? t1[m] : t0[m], k >> 1);
                a0[m] += tk * w.x;
                a1[m] += tk * w.y;
            }
        }
#pragma unroll
        for (int m = 0; m < 4; m++) {
            float v0 = fmaxf(a0[m], 0.f);   // outer relu from reference
            float v1 = fmaxf(a1[m], 0.f);
            int g = batch[n0 + m];
            float* p = g_sums + g * 64 + j;
            asm volatile("red.global.add.v2.f32 [%0], {%1, %2};"
                         :: "l"(p), "f"(v0), "f"(v1) : "memory");
            if (lane == 0) atomicAdd(&g_cnt[g], 1.0f);
        }
    }
}

// ---------------- final FC: pooled[G,64] @ Wfc[64,12] + bfc -----------------
__global__ void fc_kernel(const float* __restrict__ Wfc,
                          const float* __restrict__ bfc,
                          float* __restrict__ out) {
    int i = blockIdx.x * blockDim.x + threadIdx.x;
    if (i >= N_GRAPHS * 12) return;
    int g = i / 12;
    int c = i % 12;
    float inv = 1.0f / fmaxf(g_cnt[g], 1.0f);
    float acc = 0.f;
#pragma unroll
    for (int k = 0; k < 64; k++)
        acc += g_sums[g * 64 + k] * Wfc[k * 12 + c];
    out[i] = bfc[c] + inv * acc;
}

// ---------------- launch ----------------------------------------------------
extern "C" void kernel_launch(void* const* d_in, const int* in_sizes, int n_in,
                              void* d_out, int out_size) {
    const float* x    = (const float*)d_in[0];
    const float* ea   = (const float*)d_in[1];
    const int*   ei   = (const int*)  d_in[2];
    const int*   batch= (const int*)  d_in[3];
    const float* We1  = (const float*)d_in[4];
    const float* be1  = (const float*)d_in[5];
    const float* W1a  = (const float*)d_in[6];
    const float* b1a  = (const float*)d_in[7];
    const float* W1b  = (const float*)d_in[8];
    const float* b1b  = (const float*)d_in[9];
    const float* We2  = (const float*)d_in[10];
    const float* be2  = (const float*)d_in[11];
    const float* W2a  = (const float*)d_in[12];
    const float* b2a  = (const float*)d_in[13];
    const float* W2b  = (const float*)d_in[14];
    const float* b2b  = (const float*)d_in[15];
    const float* Wfc  = (const float*)d_in[16];
    const float* bfc  = (const float*)d_in[17];
    float* out = (float*)d_out;

    zero_kernel<<<(ZERO_TOTAL4 + 255) / 256, 256>>>(x);
    edge1_kernel<<<1184, 256>>>(ea, ei, We1, be1);
    node1_kernel<<<592, 256>>>(W1a, b1a, W1b, b1b);
    edge2_kernel<<<(N_EDGES / E2_EPW) * 16 / 256, 256>>>(ea, ei, We2, be2);
    node2pool_kernel<<<592, 256>>>(batch, W2a, b2a, W2b, b2b);
    fc_kernel<<<(N_GRAPHS * 12 + 255) / 256, 256>>>(Wfc, bfc, out);
}